// round 10
// baseline (speedup 1.0000x reference)
#include <cuda_runtime.h>

// LambdaRankLoss N=8192, 5 integer classes (0..4), SIGMA=1.
//
//   e = exp(p), g = 2^t, d = 1/log2(rank+1), rank = stable ascending-by-target.
//   lambda_i = scale * ( e_i * T1_i - T2_i ),  scale = 1/maxDCG
//   T1_i = sum_c (G_c - g_i) * ( d_i * Q_c + S_c ),
//          Q_c = sum_{j in c} r_ij,  S_c = sum_{j in c} (-d_j) r_ij,
//          r_ij = 1/(e_i + e_j)
//   T2_i = sum_{c < v_i} (G_c - g_i)(n_c d_i - SD_c)     [O(1), reduce]
//
// CLASS-ALIGNED PADDING: sorted array padded so each class starts on a
// 128 boundary; pad slots hold e=+inf (rcp -> 0, contributes exactly 0).
// Every j-tile is single-class -> inner loop is a STATIC 128-trip loop,
// 4-op body (3 fma-pipe + 1 MUFU), zero dynamic-loop overhead.

#define N      8192
#define NWARPS (N / 32)      // 256
#define K_DCG  512
#define NT     70            // padded tiles (>= 8192/128 + 5)
#define NPAD   (NT * 128)    // 8960
#define RBLK   256
#define NRB    (NPAD / RBLK) // 35
#define PAIR_T 128
#define PBLK   32

__device__ float2 g_sed[NPAD];       // padded-sorted (e, -decay); pad = (inf, 0)
__device__ int    g_inv[NPAD];       // padded pos -> original index; pad = -1
__device__ int    g_seg[8];          // TRUE class segment bounds
__device__ int    g_pbase[8];        // PADDED class segment bases
__device__ float  g_tGc[NT];         // per-tile class gain 2^c (pad tiles: 1.0)
__device__ int    g_wcnt[NWARPS][8];
__device__ int    g_wpre[NWARPS][8];
__device__ float  g_pSD[PBLK][5];
__device__ float  g_pDCG[PBLK];
__device__ float2 g_part[NT][NPAD / 2];

__device__ __forceinline__ float frcp(float x) {
    float r;
    asm("rcp.approx.f32 %0, %1;" : "=f"(r) : "f"(x));
    return r;
}

// ---------------- prep 1: per-warp class counts + clear padding ------------
__global__ void __launch_bounds__(256)
prep_count(const float* __restrict__ tgt) {
    const int i    = blockIdx.x * 256 + threadIdx.x;
    const int lane = threadIdx.x & 31;
    const int gw   = i >> 5;

    // clear whole padded array to (inf, 0) / -1; scatter overwrites real slots
    const float2 padval = make_float2(__int_as_float(0x7F800000), 0.0f);
    g_sed[i] = padval;
    g_inv[i] = -1;
    if (i < NPAD - N) {
        g_sed[N + i] = padval;
        g_inv[N + i] = -1;
    }

    int v = (int)tgt[i];
    v = max(0, min(4, v));
    #pragma unroll
    for (int c = 0; c < 5; c++) {
        unsigned b = __ballot_sync(0xffffffffu, v == c);
        if (lane == c) g_wcnt[gw][c] = __popc(b);
    }
}

// ---------------- prep 2: scan warp counts -> g_wpre, g_seg, g_pbase, tGc --
__global__ void __launch_bounds__(256)
prep_scan() {
    __shared__ int s[5][NWARPS];
    __shared__ int s_base[6];

    const int t = threadIdx.x;
    int own[5];
    #pragma unroll
    for (int c = 0; c < 5; c++) { own[c] = g_wcnt[t][c]; s[c][t] = own[c]; }
    __syncthreads();

    for (int ofs = 1; ofs < NWARPS; ofs <<= 1) {
        int a[5] = {0, 0, 0, 0, 0};
        if (t >= ofs) {
            #pragma unroll
            for (int c = 0; c < 5; c++) a[c] = s[c][t - ofs];
        }
        __syncthreads();
        #pragma unroll
        for (int c = 0; c < 5; c++) s[c][t] += a[c];
        __syncthreads();
    }

    if (t == 0) {
        int run = 0, prun = 0;
        int pb[6];
        #pragma unroll
        for (int c = 0; c < 5; c++) {
            int nc = s[c][NWARPS - 1];
            s_base[c]  = run;
            g_seg[c]   = run;
            pb[c]      = prun;
            g_pbase[c] = prun;
            run  += nc;
            prun += ((nc + 127) / 128) * 128;
        }
        g_seg[5]   = N;
        pb[5]      = prun;
        g_pbase[5] = prun;
        // per-tile class gain
        for (int tl = 0; tl < NT; tl++) {
            int start = tl * 128;
            float gc = 1.0f;                       // pad tiles: harmless finite
            #pragma unroll
            for (int c = 0; c < 5; c++)
                if (start >= pb[c] && start < pb[c + 1]) gc = (float)(1 << c);
            g_tGc[tl] = gc;
        }
    }
    __syncthreads();

    #pragma unroll
    for (int c = 0; c < 5; c++)
        g_wpre[t][c] = s_base[c] + s[c][t] - own[c];       // exclusive (true pos)
}

// ---------------- prep 3: scatter to PADDED sorted order + SD/DCG ----------
__global__ void __launch_bounds__(256)
prep_scatter(const float* __restrict__ pred, const float* __restrict__ tgt) {
    __shared__ float s_sd[8][5];
    __shared__ float s_dcg[8];

    const int i    = blockIdx.x * 256 + threadIdx.x;
    const int lane = threadIdx.x & 31;
    const int wid  = threadIdx.x >> 5;
    const int gw   = i >> 5;

    int v = (int)tgt[i];
    v = max(0, min(4, v));

    int intra = 0;
    #pragma unroll
    for (int c = 0; c < 5; c++) {
        unsigned b = __ballot_sync(0xffffffffu, v == c);
        if (v == c) intra = __popc(b & ((1u << lane) - 1u));
    }
    const int k  = g_wpre[gw][v] + intra;                  // TRUE sorted pos
    const int kp = g_pbase[v] + (k - g_seg[v]);            // PADDED pos

    const float e = __expf(pred[i]);
    const float d = __fdividef(1.0f, log2f((float)k + 2.0f));
    g_sed[kp] = make_float2(e, -d);
    g_inv[kp] = i;

    float term = 0.0f;
    if (k >= N - K_DCG) {
        int r = N - k;                                     // descending rank
        term = (exp2f((float)v) - 1.0f) / log2f((float)r + 1.0f);
    }

    #pragma unroll
    for (int c = 0; c < 5; c++) {
        float x = (v == c) ? d : 0.0f;
        #pragma unroll
        for (int o = 16; o > 0; o >>= 1)
            x += __shfl_down_sync(0xffffffffu, x, o);
        if (lane == 0) s_sd[wid][c] = x;
    }
    {
        float x = term;
        #pragma unroll
        for (int o = 16; o > 0; o >>= 1)
            x += __shfl_down_sync(0xffffffffu, x, o);
        if (lane == 0) s_dcg[wid] = x;
    }
    __syncthreads();

    if (threadIdx.x < 5) {
        float s = 0.0f;
        #pragma unroll
        for (int w = 0; w < 8; w++) s += s_sd[w][threadIdx.x];
        g_pSD[blockIdx.x][threadIdx.x] = s;
    } else if (threadIdx.x == 5) {
        float s = 0.0f;
        #pragma unroll
        for (int w = 0; w < 8; w++) s += s_dcg[w];
        g_pDCG[blockIdx.x] = s;
    }
}

// ---------------- pairwise: grid (NRB, NT); STATIC 128-trip inner loop -----
__global__ void __launch_bounds__(PAIR_T)
pair_kernel() {
    const int t  = threadIdx.x;
    const int r0 = blockIdx.x * RBLK + 2 * t;
    const int r1 = r0 + 1;

    const int pb1 = g_pbase[1], pb2 = g_pbase[2],
              pb3 = g_pbase[3], pb4 = g_pbase[4];

    const float2 a0 = g_sed[r0];
    const float2 a1 = g_sed[r1];
    const float e0 = a0.x, d0 = -a0.y;
    const float e1 = a1.x, d1 = -a1.y;
    const int v0 = (r0 >= pb1) + (r0 >= pb2) + (r0 >= pb3) + (r0 >= pb4);
    const int v1 = (r1 >= pb1) + (r1 >= pb2) + (r1 >= pb3) + (r1 >= pb4);

    const float Gc    = g_tGc[blockIdx.y];
    const float coef0 = Gc - (float)(1 << v0);
    const float coef1 = Gc - (float)(1 << v1);

    float2 res = make_float2(0.0f, 0.0f);

    if (!__all_sync(0xffffffffu, (coef0 == 0.0f) && (coef1 == 0.0f))) {
        const float2* __restrict__ p = g_sed + blockIdx.y * 128;

        float Q0 = 0.f, S0 = 0.f, Q1 = 0.f, S1 = 0.f;

        #pragma unroll 8
        for (int j = 0; j < 128; j++) {
            const float2 w = __ldg(p + j);       // warp-uniform -> broadcast
            float ra = frcp(e0 + w.x);           // pad: rcp(inf) = 0
            float rb = frcp(e1 + w.x);
            Q0 += ra;
            S0 = fmaf(w.y, ra, S0);
            Q1 += rb;
            S1 = fmaf(w.y, rb, S1);
        }
        res.x = coef0 * fmaf(d0, Q0, S0);
        res.y = coef1 * fmaf(d1, Q1, S1);
    }

    g_part[blockIdx.y][blockIdx.x * (RBLK / 2) + t] = res;
}

// ---------------- reduce: finish SD/DCG, T1 + analytic T2, scatter ---------
__global__ void __launch_bounds__(256)
reduce_kernel(float* __restrict__ out) {
    __shared__ float s_scale;
    __shared__ float s_SD[5];

    const int t    = threadIdx.x;
    const int lane = t & 31;
    const int wid  = t >> 5;

    if (wid == 0) {
        float x = g_pDCG[lane];                    // PBLK == 32
        #pragma unroll
        for (int o = 16; o > 0; o >>= 1)
            x += __shfl_down_sync(0xffffffffu, x, o);
        if (lane == 0) s_scale = __fdividef(1.0f, x);
    } else if (wid <= 5) {
        float x = g_pSD[lane][wid - 1];
        #pragma unroll
        for (int o = 16; o > 0; o >>= 1)
            x += __shfl_down_sync(0xffffffffu, x, o);
        if (lane == 0) s_SD[wid - 1] = x;
    }
    __syncthreads();

    const int kp  = blockIdx.x * 256 + t;          // padded position
    const int idx = g_inv[kp];
    if (idx < 0) return;                           // padding slot

    float T1 = 0.0f;
    #pragma unroll
    for (int s = 0; s < NT; s++)
        T1 += ((const float*)g_part[s])[kp];

    const int pb1 = g_pbase[1], pb2 = g_pbase[2],
              pb3 = g_pbase[3], pb4 = g_pbase[4];
    const int v = (kp >= pb1) + (kp >= pb2) + (kp >= pb3) + (kp >= pb4);

    const float2 a = g_sed[kp];
    const float e = a.x;
    const float d = -a.y;
    const float g = (float)(1 << v);

    float T2 = 0.0f;
    #pragma unroll
    for (int c = 0; c < 4; c++) {
        if (c < v) {
            float nc = (float)(g_seg[c + 1] - g_seg[c]);
            T2 += ((float)(1 << c) - g) * (nc * d - s_SD[c]);
        }
    }

    out[idx] = s_scale * (e * T1 - T2);
}

extern "C" void kernel_launch(void* const* d_in, const int* in_sizes, int n_in,
                              void* d_out, int out_size) {
    const float* pred = (const float*)d_in[0];
    const float* tgt  = (const float*)d_in[1];
    float* out        = (float*)d_out;

    prep_count<<<PBLK, 256>>>(tgt);
    prep_scan<<<1, 256>>>();
    prep_scatter<<<PBLK, 256>>>(pred, tgt);
    dim3 grid(NRB, NT);
    pair_kernel<<<grid, PAIR_T>>>();
    reduce_kernel<<<NPAD / 256, 256>>>(out);
}

// round 11
// speedup vs baseline: 1.1032x; 1.1032x over previous
#include <cuda_runtime.h>

// LambdaRankLoss N=8192, 5 integer classes (0..4), SIGMA=1.
//
//   e = exp(p), g = 2^t, d = 1/log2(rank+1), rank = stable ascending-by-target.
//   lambda_i = scale * ( e_i * T1_i - T2_i ),  scale = 1/maxDCG
//   T1_i = sum_j (g_j - g_i)(d_i - d_j)/(e_i + e_j)
//        = sum_c (G_c - g_i) * sum_{j in c} (d_i - d_j) * r_ij
//   T2_i = sum_{c < v_i} (G_c - g_i)(n_c d_i - SD_c)     [O(1), reduce]
//
// CLASS-ALIGNED PADDING (pad e = 1e18, finite!): every 128-wide j-tile is
// single-class -> static 128-trip inner loop.
// RCP-MERGE: rp = rcp(s0*s1); 1/s0 = rp*s1, 1/s1 = rp*s0 -> ONE MUFU per
// two pairs (rows share each j). Pad rows still recover the real row's
// reciprocal exactly; pad j contributes ~1e-18 per slot (negligible).

#define N      8192
#define NWARPS (N / 32)      // 256
#define K_DCG  512
#define NT     70            // padded tiles
#define NPAD   (NT * 128)    // 8960
#define RBLK   256
#define NRB    (NPAD / RBLK) // 35
#define PAIR_T 128
#define PBLK   32
#define PADE   1.0e18f

__device__ float2 g_sed[NPAD];       // padded-sorted (e, -decay); pad = (1e18, 0)
__device__ int    g_inv[NPAD];       // padded pos -> original index; pad = -1
__device__ int    g_seg[8];          // TRUE class segment bounds
__device__ int    g_pbase[8];        // PADDED class segment bases
__device__ float  g_tGc[NT];         // per-tile class gain 2^c
__device__ int    g_wcnt[NWARPS][8];
__device__ int    g_wpre[NWARPS][8];
__device__ float  g_pSD[PBLK][5];
__device__ float  g_pDCG[PBLK];
__device__ float2 g_part[NT][NPAD / 2];

__device__ __forceinline__ float frcp(float x) {
    float r;
    asm("rcp.approx.f32 %0, %1;" : "=f"(r) : "f"(x));
    return r;
}

// ---------------- prep 1: per-warp class counts + clear padding ------------
__global__ void __launch_bounds__(256)
prep_count(const float* __restrict__ tgt) {
    const int i    = blockIdx.x * 256 + threadIdx.x;
    const int lane = threadIdx.x & 31;
    const int gw   = i >> 5;

    const float2 padval = make_float2(PADE, 0.0f);
    g_sed[i] = padval;
    g_inv[i] = -1;
    if (i < NPAD - N) {
        g_sed[N + i] = padval;
        g_inv[N + i] = -1;
    }

    int v = (int)tgt[i];
    v = max(0, min(4, v));
    #pragma unroll
    for (int c = 0; c < 5; c++) {
        unsigned b = __ballot_sync(0xffffffffu, v == c);
        if (lane == c) g_wcnt[gw][c] = __popc(b);
    }
}

// ---------------- prep 2: scan warp counts -> g_wpre, g_seg, g_pbase, tGc --
__global__ void __launch_bounds__(256)
prep_scan() {
    __shared__ int s[5][NWARPS];
    __shared__ int s_base[6];

    const int t = threadIdx.x;
    int own[5];
    #pragma unroll
    for (int c = 0; c < 5; c++) { own[c] = g_wcnt[t][c]; s[c][t] = own[c]; }
    __syncthreads();

    for (int ofs = 1; ofs < NWARPS; ofs <<= 1) {
        int a[5] = {0, 0, 0, 0, 0};
        if (t >= ofs) {
            #pragma unroll
            for (int c = 0; c < 5; c++) a[c] = s[c][t - ofs];
        }
        __syncthreads();
        #pragma unroll
        for (int c = 0; c < 5; c++) s[c][t] += a[c];
        __syncthreads();
    }

    if (t == 0) {
        int run = 0, prun = 0;
        int pb[6];
        #pragma unroll
        for (int c = 0; c < 5; c++) {
            int nc = s[c][NWARPS - 1];
            s_base[c]  = run;
            g_seg[c]   = run;
            pb[c]      = prun;
            g_pbase[c] = prun;
            run  += nc;
            prun += ((nc + 127) / 128) * 128;
        }
        g_seg[5]   = N;
        pb[5]      = prun;
        g_pbase[5] = prun;
        for (int tl = 0; tl < NT; tl++) {
            int start = tl * 128;
            float gc = 1.0f;
            #pragma unroll
            for (int c = 0; c < 5; c++)
                if (start >= pb[c] && start < pb[c + 1]) gc = (float)(1 << c);
            g_tGc[tl] = gc;
        }
    }
    __syncthreads();

    #pragma unroll
    for (int c = 0; c < 5; c++)
        g_wpre[t][c] = s_base[c] + s[c][t] - own[c];       // exclusive (true pos)
}

// ---------------- prep 3: scatter to PADDED sorted order + SD/DCG ----------
__global__ void __launch_bounds__(256)
prep_scatter(const float* __restrict__ pred, const float* __restrict__ tgt) {
    __shared__ float s_sd[8][5];
    __shared__ float s_dcg[8];

    const int i    = blockIdx.x * 256 + threadIdx.x;
    const int lane = threadIdx.x & 31;
    const int wid  = threadIdx.x >> 5;
    const int gw   = i >> 5;

    int v = (int)tgt[i];
    v = max(0, min(4, v));

    int intra = 0;
    #pragma unroll
    for (int c = 0; c < 5; c++) {
        unsigned b = __ballot_sync(0xffffffffu, v == c);
        if (v == c) intra = __popc(b & ((1u << lane) - 1u));
    }
    const int k  = g_wpre[gw][v] + intra;                  // TRUE sorted pos
    const int kp = g_pbase[v] + (k - g_seg[v]);            // PADDED pos

    const float e = __expf(pred[i]);
    const float d = __fdividef(1.0f, log2f((float)k + 2.0f));
    g_sed[kp] = make_float2(e, -d);
    g_inv[kp] = i;

    float term = 0.0f;
    if (k >= N - K_DCG) {
        int r = N - k;                                     // descending rank
        term = (exp2f((float)v) - 1.0f) / log2f((float)r + 1.0f);
    }

    #pragma unroll
    for (int c = 0; c < 5; c++) {
        float x = (v == c) ? d : 0.0f;
        #pragma unroll
        for (int o = 16; o > 0; o >>= 1)
            x += __shfl_down_sync(0xffffffffu, x, o);
        if (lane == 0) s_sd[wid][c] = x;
    }
    {
        float x = term;
        #pragma unroll
        for (int o = 16; o > 0; o >>= 1)
            x += __shfl_down_sync(0xffffffffu, x, o);
        if (lane == 0) s_dcg[wid] = x;
    }
    __syncthreads();

    if (threadIdx.x < 5) {
        float s = 0.0f;
        #pragma unroll
        for (int w = 0; w < 8; w++) s += s_sd[w][threadIdx.x];
        g_pSD[blockIdx.x][threadIdx.x] = s;
    } else if (threadIdx.x == 5) {
        float s = 0.0f;
        #pragma unroll
        for (int w = 0; w < 8; w++) s += s_dcg[w];
        g_pDCG[blockIdx.x] = s;
    }
}

// ---------------- pairwise: static 128-trip loop, merged reciprocals -------
__global__ void __launch_bounds__(PAIR_T)
pair_kernel() {
    const int t  = threadIdx.x;
    const int r0 = blockIdx.x * RBLK + 2 * t;
    const int r1 = r0 + 1;

    const int pb1 = g_pbase[1], pb2 = g_pbase[2],
              pb3 = g_pbase[3], pb4 = g_pbase[4];

    const float2 a0 = g_sed[r0];
    const float2 a1 = g_sed[r1];
    const float e0 = a0.x, d0 = -a0.y;
    const float e1 = a1.x, d1 = -a1.y;
    const int v0 = (r0 >= pb1) + (r0 >= pb2) + (r0 >= pb3) + (r0 >= pb4);
    const int v1 = (r1 >= pb1) + (r1 >= pb2) + (r1 >= pb3) + (r1 >= pb4);

    const float Gc    = g_tGc[blockIdx.y];
    const float coef0 = Gc - (float)(1 << v0);
    const float coef1 = Gc - (float)(1 << v1);

    float2 res = make_float2(0.0f, 0.0f);

    if (!__all_sync(0xffffffffu, (coef0 == 0.0f) && (coef1 == 0.0f))) {
        const float2* __restrict__ p = g_sed + blockIdx.y * 128;

        float A0a = 0.f, A0b = 0.f, A1a = 0.f, A1b = 0.f;

        #pragma unroll 8
        for (int j = 0; j < 128; j += 2) {
            const float2 wa = __ldg(p + j);        // warp-uniform -> broadcast
            const float2 wb = __ldg(p + j + 1);
            {
                float s0  = e0 + wa.x;
                float s1  = e1 + wa.x;
                float rp  = frcp(s0 * s1);          // ONE rcp for both rows
                float dd0 = d0 + wa.y;              // d_i - d_j
                float dd1 = d1 + wa.y;
                A0a = fmaf(dd0, rp * s1, A0a);      // dd0 / s0
                A1a = fmaf(dd1, rp * s0, A1a);      // dd1 / s1
            }
            {
                float s0  = e0 + wb.x;
                float s1  = e1 + wb.x;
                float rp  = frcp(s0 * s1);
                float dd0 = d0 + wb.y;
                float dd1 = d1 + wb.y;
                A0b = fmaf(dd0, rp * s1, A0b);
                A1b = fmaf(dd1, rp * s0, A1b);
            }
        }
        res.x = coef0 * (A0a + A0b);
        res.y = coef1 * (A1a + A1b);
    }

    g_part[blockIdx.y][blockIdx.x * (RBLK / 2) + t] = res;
}

// ---------------- reduce: finish SD/DCG, T1 + analytic T2, scatter ---------
__global__ void __launch_bounds__(256)
reduce_kernel(float* __restrict__ out) {
    __shared__ float s_scale;
    __shared__ float s_SD[5];

    const int t    = threadIdx.x;
    const int lane = t & 31;
    const int wid  = t >> 5;

    if (wid == 0) {
        float x = g_pDCG[lane];                    // PBLK == 32
        #pragma unroll
        for (int o = 16; o > 0; o >>= 1)
            x += __shfl_down_sync(0xffffffffu, x, o);
        if (lane == 0) s_scale = __fdividef(1.0f, x);
    } else if (wid <= 5) {
        float x = g_pSD[lane][wid - 1];
        #pragma unroll
        for (int o = 16; o > 0; o >>= 1)
            x += __shfl_down_sync(0xffffffffu, x, o);
        if (lane == 0) s_SD[wid - 1] = x;
    }
    __syncthreads();

    const int kp  = blockIdx.x * 256 + t;          // padded position
    const int idx = g_inv[kp];
    if (idx < 0) return;                           // padding slot

    float T1 = 0.0f;
    #pragma unroll
    for (int s = 0; s < NT; s++)
        T1 += ((const float*)g_part[s])[kp];

    const int pb1 = g_pbase[1], pb2 = g_pbase[2],
              pb3 = g_pbase[3], pb4 = g_pbase[4];
    const int v = (kp >= pb1) + (kp >= pb2) + (kp >= pb3) + (kp >= pb4);

    const float2 a = g_sed[kp];
    const float e = a.x;
    const float d = -a.y;
    const float g = (float)(1 << v);

    float T2 = 0.0f;
    #pragma unroll
    for (int c = 0; c < 4; c++) {
        if (c < v) {
            float nc = (float)(g_seg[c + 1] - g_seg[c]);
            T2 += ((float)(1 << c) - g) * (nc * d - s_SD[c]);
        }
    }

    out[idx] = s_scale * (e * T1 - T2);
}

extern "C" void kernel_launch(void* const* d_in, const int* in_sizes, int n_in,
                              void* d_out, int out_size) {
    const float* pred = (const float*)d_in[0];
    const float* tgt  = (const float*)d_in[1];
    float* out        = (float*)d_out;

    prep_count<<<PBLK, 256>>>(tgt);
    prep_scan<<<1, 256>>>();
    prep_scatter<<<PBLK, 256>>>(pred, tgt);
    dim3 grid(NRB, NT);
    pair_kernel<<<grid, PAIR_T>>>();
    reduce_kernel<<<NPAD / 256, 256>>>(out);
}